// round 2
// baseline (speedup 1.0000x reference)
#include <cuda_runtime.h>
#include <math.h>

// CapsuleRouting: u (4,288,32,16,14,14) f32, a unused.
// out = concat(v (4,32,16,14,14), a_out (4,32,14,14))

#define BD 4      // batch
#define NB 288    // input capsules
#define NC 32     // output capsules (softmax axis)
#define NP 16     // pose dim
#define HW 196    // h*w
#define NCHUNK 4
#define BCH (NB / NCHUNK)   // 72
#define EPSF 1e-5f

// ---------------- scratch (static device globals; no runtime alloc) ----------
__device__ float g_S0p[NCHUNK * BD * NC * NP * HW];   // 6.4 MB partial sums
__device__ float g_mxp[NCHUNK * BD * NC * HW];
__device__ float g_mnp[NCHUNK * BD * NC * HW];
__device__ float g_v   [BD * NC * NP * HW];           // v0 then v1 (reused)
__device__ float g_invd[BD * NC * HW];
__device__ float g_r   [(size_t)BD * NB * NC * HW];   // 28.9 MB routing logits
__device__ float g_w   [(size_t)BD * NB * NC * HW];   // 28.9 MB softmax weights
__device__ float g_S   [BD * NC * NP * HW];           // weighted sums

// ---------------- Pass A1: per-(B,c,hw) norms -> chunked max/min; Sum_B u ----
__global__ void kA1(const float* __restrict__ u) {
    int t = blockIdx.x * blockDim.x + threadIdx.x;    // 100352
    int hw = t % HW;
    int rest = t / HW;
    int c = rest % NC; rest /= NC;
    int b = rest % BD;
    int ch = rest / BD;

    float s[NP];
#pragma unroll
    for (int p = 0; p < NP; p++) s[p] = 0.0f;
    float mx = -1e30f, mn = 1e30f;

    const float* up = u + ((size_t)((b * NB + ch * BCH) * NC + c)) * (NP * HW) + hw;
    for (int i = 0; i < BCH; i++) {
        float nrm = EPSF;
#pragma unroll
        for (int p = 0; p < NP; p++) {
            float x = up[p * HW];
            s[p] += x;
            nrm += x * x;
        }
        nrm = sqrtf(nrm);
        mx = fmaxf(mx, nrm);
        mn = fminf(mn, nrm);
        up += (size_t)NC * NP * HW;  // next B
    }
    int o = (ch * BD + b) * NC + c;
#pragma unroll
    for (int p = 0; p < NP; p++) g_S0p[(o * NP + p) * HW + hw] = s[p];
    g_mxp[o * HW + hw] = mx;
    g_mnp[o * HW + hw] = mn;
}

// ---------------- Pass A2: combine chunks, inv_d, v0 = squash(S0*inv_d/32) ---
__global__ void kA2() {
    int t = blockIdx.x * blockDim.x + threadIdx.x;    // 25088
    int hw = t % HW;
    int rest = t / HW;
    int c = rest % NC;
    int b = rest / NC;

    float s[NP];
#pragma unroll
    for (int p = 0; p < NP; p++) s[p] = 0.0f;
    float mx = -1e30f, mn = 1e30f;
#pragma unroll
    for (int ch = 0; ch < NCHUNK; ch++) {
        int o = (ch * BD + b) * NC + c;
        mx = fmaxf(mx, g_mxp[o * HW + hw]);
        mn = fminf(mn, g_mnp[o * HW + hw]);
#pragma unroll
        for (int p = 0; p < NP; p++) s[p] += g_S0p[(o * NP + p) * HW + hw];
    }
    float invd = 1.0f / (mx - mn);
    g_invd[(b * NC + c) * HW + hw] = invd;

    float nv = EPSF;
    const float scl = invd * (1.0f / (float)NC);   // uniform softmax weight 1/32
#pragma unroll
    for (int p = 0; p < NP; p++) { s[p] *= scl; nv += s[p] * s[p]; }
    nv = sqrtf(nv);
    float f = 1.0f / (1.0f + nv);
#pragma unroll
    for (int p = 0; p < NP; p++) g_v[((b * NC + c) * NP + p) * HW + hw] = s[p] * f;
}

// ---------------- Pass B1: r += inv_d*(u.v);  w = softmax_c(r) ---------------
template <int PHASE>
__global__ void kB1(const float* __restrict__ u) {
    int t = blockIdx.x * blockDim.x + threadIdx.x;    // 225792
    int hw = t % HW;
    int rest = t / HW;
    int B = rest % NB;
    int b = rest / NB;

    const float* ub  = u      + ((size_t)(b * NB + B) * NC) * (NP * HW) + hw;
    const float* vb  = g_v    + ((size_t)(b * NC)) * (NP * HW) + hw;
    const float* idb = g_invd + ((size_t)(b * NC)) * HW + hw;
    size_t rbase = ((size_t)(b * NB + B) * NC) * HW + hw;

    float r[NC];
#pragma unroll
    for (int c = 0; c < NC; c++) {
        float dot = 0.0f;
#pragma unroll
        for (int p = 0; p < NP; p++)
            dot += ub[(c * NP + p) * HW] * vb[(c * NP + p) * HW];
        float rc = idb[c * HW] * dot;
        if (PHASE == 2) rc += g_r[rbase + (size_t)c * HW];
        if (PHASE == 1) g_r[rbase + (size_t)c * HW] = rc;  // raw logits for next iter
        r[c] = rc;
    }
    float m = r[0];
#pragma unroll
    for (int c = 1; c < NC; c++) m = fmaxf(m, r[c]);
    float ssum = 0.0f;
#pragma unroll
    for (int c = 0; c < NC; c++) { r[c] = __expf(r[c] - m); ssum += r[c]; }
    float inv = 1.0f / ssum;
#pragma unroll
    for (int c = 0; c < NC; c++) g_w[rbase + (size_t)c * HW] = r[c] * inv;
}

// ---------------- Pass B2: S[c,p,hw] = Sum_B w[B,c,hw] * u[B,c,p,hw] ---------
__global__ void kB2(const float* __restrict__ u) {
    int t = blockIdx.x * blockDim.x + threadIdx.x;    // 401408
    int hw = t % HW;
    int rest = t / HW;
    int p = rest % NP; rest /= NP;
    int c = rest % NC;
    int b = rest / NC;

    const float* ub = u   + (((size_t)(b * NB) * NC + c) * NP + p) * HW + hw;
    const float* wb = g_w + ((size_t)(b * NB) * NC + c) * HW + hw;

    float acc = 0.0f;
#pragma unroll 4
    for (int B = 0; B < NB; B++) {
        acc += wb[(size_t)B * NC * HW] * ub[(size_t)B * NC * NP * HW];
    }
    g_S[t] = acc;
}

// ---------------- Squash / final output --------------------------------------
__global__ void kFin(float* __restrict__ vout, float* __restrict__ aout, int last) {
    int t = blockIdx.x * blockDim.x + threadIdx.x;    // 25088
    int hw = t % HW;
    int rest = t / HW;
    int c = rest % NC;
    int b = rest / NC;

    float invd = g_invd[(b * NC + c) * HW + hw];
    float s[NP];
    float nv = EPSF;
#pragma unroll
    for (int p = 0; p < NP; p++) {
        s[p] = g_S[((b * NC + c) * NP + p) * HW + hw] * invd;
        nv += s[p] * s[p];
    }
    nv = sqrtf(nv);
    float f = 1.0f / (1.0f + nv);
    if (!last) {
#pragma unroll
        for (int p = 0; p < NP; p++)
            g_v[((b * NC + c) * NP + p) * HW + hw] = s[p] * f;
    } else {
        float an = EPSF;
#pragma unroll
        for (int p = 0; p < NP; p++) {
            float v = s[p] * f;
            vout[((b * NC + c) * NP + p) * HW + hw] = v;
            an += v * v;
        }
        aout[(b * NC + c) * HW + hw] = sqrtf(an);
    }
}

// ---------------- launch ------------------------------------------------------
extern "C" void kernel_launch(void* const* d_in, const int* in_sizes, int n_in,
                              void* d_out, int out_size) {
    const float* u = (const float*)d_in[0];
    float* out = (float*)d_out;
    float* out_v = out;                       // 4*32*16*196 = 401408
    float* out_a = out + BD * NC * NP * HW;   // 4*32*196    = 25088

    kA1<<<392, 256>>>(u);                 // norms + Sum_B u (chunked over B)
    kA2<<<98, 256>>>();                   // inv_d, v0
    kB1<1><<<882, 256>>>(u);              // r1 = inv_d*(u.v0); w1 = softmax
    kB2<<<1568, 256>>>(u);                // S1 = Sum_B w1*u
    kFin<<<98, 256>>>(nullptr, nullptr, 0);  // v1 = squash(inv_d*S1)
    kB1<2><<<882, 256>>>(u);              // r2 = r1 + inv_d*(u.v1); w2 = softmax
    kB2<<<1568, 256>>>(u);                // S2 = Sum_B w2*u
    kFin<<<98, 256>>>(out_v, out_a, 1);   // v2, a_out
}

// round 3
// speedup vs baseline: 1.9852x; 1.9852x over previous
#include <cuda_runtime.h>
#include <cuda_fp16.h>
#include <math.h>

// CapsuleRouting: u (4,288,32,16,14,14) f32, a unused.
// out = concat(v (4,32,16,14,14), a_out (4,32,14,14))

#define BD 4      // batch
#define NB 288    // input capsules
#define NC 32     // output capsules (softmax axis)
#define NP 16     // pose dim
#define HW 196    // h*w
#define NCHUNK 4  // B-chunks in pass A
#define BCH (NB / NCHUNK)   // 72
#define EPSF 1e-5f

// F-kernel tiling
#define TH 28           // hw per block (7 tiles)
#define NPP 8           // p-pair lanes
#define FTHREADS (TH * NPP)   // 224
#define NCH2 10         // B-chunks in F pass
#define BCH2 29         // ceil(288/10)

// ---------------- scratch (static device globals) -----------------------------
__device__ __half g_u16[(size_t)BD * NB * NC * HW * NP];   // 231MB, layout (b,B,c,hw,p)
__device__ float  g_S0p[NCHUNK * BD * NC * NP * HW];
__device__ float  g_mxp[NCHUNK * BD * NC * HW];
__device__ float  g_mnp[NCHUNK * BD * NC * HW];
__device__ float  g_invd[BD * NC * HW];
__device__ __half g_vs[BD * NC * HW * NP];                 // v_s = invd*v, layout (b,c,hw,p)
__device__ float  g_r[(size_t)BD * NB * HW * NC];          // 28.9MB, layout (b,B,hw,c)
__device__ float  g_Sp[NCH2 * BD * NC * HW * NP];          // 16MB partial S, (chk,b,c,hw,p)

union HPack { __half2 h2[8]; uint4 u4[2]; };

// ---------------- Pass A1: norms -> chunked max/min; Sum_B u; emit u16 --------
__global__ void kA1(const float* __restrict__ u) {
    int t = blockIdx.x * blockDim.x + threadIdx.x;    // 100352
    int hw = t % HW;
    int rest = t / HW;
    int c = rest % NC; rest /= NC;
    int b = rest % BD;
    int ch = rest / BD;

    float s[NP];
#pragma unroll
    for (int p = 0; p < NP; p++) s[p] = 0.0f;
    float mx = -1e30f, mn = 1e30f;

    const float* up = u + ((size_t)((b * NB + ch * BCH) * NC + c)) * (NP * HW) + hw;
    size_t u16base = (((size_t)(b * NB + ch * BCH) * NC + c) * HW + hw) * NP;

    for (int i = 0; i < BCH; i++) {
        float x[NP];
        float nrm = EPSF;
#pragma unroll
        for (int p = 0; p < NP; p++) {
            x[p] = up[p * HW];
            s[p] += x[p];
            nrm += x[p] * x[p];
        }
        nrm = sqrtf(nrm);
        mx = fmaxf(mx, nrm);
        mn = fminf(mn, nrm);

        HPack pk;
#pragma unroll
        for (int j = 0; j < 8; j++) pk.h2[j] = __floats2half2_rn(x[2 * j], x[2 * j + 1]);
        uint4* dst = reinterpret_cast<uint4*>(g_u16 + u16base);
        dst[0] = pk.u4[0];
        dst[1] = pk.u4[1];

        up += (size_t)NC * NP * HW;          // next B
        u16base += (size_t)NC * HW * NP;
    }
    int o = (ch * BD + b) * NC + c;
#pragma unroll
    for (int p = 0; p < NP; p++) g_S0p[(o * NP + p) * HW + hw] = s[p];
    g_mxp[o * HW + hw] = mx;
    g_mnp[o * HW + hw] = mn;
}

// ---------------- Pass A2: combine chunks, inv_d, v0s = invd*squash(S0/32*invd)
__global__ void kA2() {
    int t = blockIdx.x * blockDim.x + threadIdx.x;    // 25088
    int hw = t % HW;
    int rest = t / HW;
    int c = rest % NC;
    int b = rest / NC;

    float s[NP];
#pragma unroll
    for (int p = 0; p < NP; p++) s[p] = 0.0f;
    float mx = -1e30f, mn = 1e30f;
#pragma unroll
    for (int ch = 0; ch < NCHUNK; ch++) {
        int o = (ch * BD + b) * NC + c;
        mx = fmaxf(mx, g_mxp[o * HW + hw]);
        mn = fminf(mn, g_mnp[o * HW + hw]);
#pragma unroll
        for (int p = 0; p < NP; p++) s[p] += g_S0p[(o * NP + p) * HW + hw];
    }
    float invd = 1.0f / (mx - mn);
    g_invd[(b * NC + c) * HW + hw] = invd;

    float nv = EPSF;
    const float scl = invd * (1.0f / (float)NC);   // uniform softmax weight 1/32
#pragma unroll
    for (int p = 0; p < NP; p++) { s[p] *= scl; nv += s[p] * s[p]; }
    nv = sqrtf(nv);
    float f = invd / (1.0f + nv);                  // fold invd into stored v_s
    HPack pk;
#pragma unroll
    for (int j = 0; j < 8; j++)
        pk.h2[j] = __floats2half2_rn(s[2 * j] * f, s[2 * j + 1] * f);
    uint4* dst = reinterpret_cast<uint4*>(g_vs + ((size_t)((b * NC + c) * HW + hw)) * NP);
    dst[0] = pk.u4[0];
    dst[1] = pk.u4[1];
}

// ---------------- Fused routing iteration: read u16 once ----------------------
// r_new = (r_old +) dot(u, v_s); w = softmax_c(r_new); S_partial += w*u
template <int PHASE>
__global__ void __launch_bounds__(FTHREADS, 2) kF() {
    int bid = blockIdx.x;
    int chk = bid % NCH2;
    int hwt = (bid / NCH2) % (HW / TH);
    int b   = bid / (NCH2 * (HW / TH));

    int tid = threadIdx.x;
    int pp  = tid & (NPP - 1);        // p-pair lane 0..7
    int hwl = tid >> 3;               // 0..27
    int hw  = hwt * TH + hwl;

    __shared__ __half2 vsm[NC][TH][NPP];
    for (int i = tid; i < NC * TH * NPP; i += FTHREADS) {
        int c  = i / (TH * NPP);
        int r  = i % (TH * NPP);
        int hl = r / NPP;
        int p2 = r % NPP;
        vsm[c][hl][p2] = *reinterpret_cast<const __half2*>(
            g_vs + (((size_t)(b * NC + c) * HW + hwt * TH + hl)) * NP + 2 * p2);
    }
    __syncthreads();

    float2 S2[NC];
#pragma unroll
    for (int c = 0; c < NC; c++) S2[c] = make_float2(0.0f, 0.0f);

    int B0 = chk * BCH2;
    int Bend = min(B0 + BCH2, NB);

    for (int B = B0; B < Bend; B++) {
        const __half* ub = g_u16 + ((((size_t)(b * NB + B) * NC) * HW + hw)) * NP + 2 * pp;
        __half2 x2[NC];
        float r4[4];

#pragma unroll
        for (int c = 0; c < NC; c++) {
            x2[c] = *reinterpret_cast<const __half2*>(ub + (size_t)c * (HW * NP));
            float2 xf = __half22float2(x2[c]);
            float2 vf = __half22float2(vsm[c][hwl][pp]);
            float t = xf.x * vf.x + xf.y * vf.y;
            t += __shfl_xor_sync(0xffffffffu, t, 1, 8);
            t += __shfl_xor_sync(0xffffffffu, t, 2, 8);
            t += __shfl_xor_sync(0xffffffffu, t, 4, 8);
            if ((c >> 2) == pp) r4[c & 3] = t;
        }

        float* rptr = g_r + (((size_t)(b * NB + B) * HW + hw)) * NC + 4 * pp;
        if (PHASE == 2) {
            float4 rp = *reinterpret_cast<const float4*>(rptr);
            r4[0] += rp.x; r4[1] += rp.y; r4[2] += rp.z; r4[3] += rp.w;
        } else {
            *reinterpret_cast<float4*>(rptr) = make_float4(r4[0], r4[1], r4[2], r4[3]);
        }

        // softmax over 32 c (4 per lane x 8 lanes)
        float m = fmaxf(fmaxf(r4[0], r4[1]), fmaxf(r4[2], r4[3]));
        m = fmaxf(m, __shfl_xor_sync(0xffffffffu, m, 1, 8));
        m = fmaxf(m, __shfl_xor_sync(0xffffffffu, m, 2, 8));
        m = fmaxf(m, __shfl_xor_sync(0xffffffffu, m, 4, 8));
        float w4[4];
        float ssum = 0.0f;
#pragma unroll
        for (int k = 0; k < 4; k++) { w4[k] = __expf(r4[k] - m); ssum += w4[k]; }
        ssum += __shfl_xor_sync(0xffffffffu, ssum, 1, 8);
        ssum += __shfl_xor_sync(0xffffffffu, ssum, 2, 8);
        ssum += __shfl_xor_sync(0xffffffffu, ssum, 4, 8);
        float inv = 1.0f / ssum;
#pragma unroll
        for (int k = 0; k < 4; k++) w4[k] *= inv;

        // accumulate S += w*u
#pragma unroll
        for (int c = 0; c < NC; c++) {
            float wc = __shfl_sync(0xffffffffu, w4[c & 3], c >> 2, 8);
            float2 xf = __half22float2(x2[c]);
            S2[c].x += wc * xf.x;
            S2[c].y += wc * xf.y;
        }
    }

    // write partial S
#pragma unroll
    for (int c = 0; c < NC; c++) {
        float2* dst = reinterpret_cast<float2*>(
            g_Sp + ((((size_t)(chk * BD + b) * NC + c) * HW + hw)) * NP + 2 * pp);
        *dst = S2[c];
    }
}

// ---------------- Combine partials: squash; emit v_s (half) or final output ---
template <int LAST>
__global__ void kC(float* __restrict__ vout, float* __restrict__ aout) {
    int t = blockIdx.x * blockDim.x + threadIdx.x;    // 25088
    int hw = t % HW;
    int rest = t / HW;
    int c = rest % NC;
    int b = rest / NC;

    float s[NP];
#pragma unroll
    for (int p = 0; p < NP; p++) s[p] = 0.0f;
#pragma unroll
    for (int chk = 0; chk < NCH2; chk++) {
        const float* sp = g_Sp + ((((size_t)(chk * BD + b) * NC + c) * HW + hw)) * NP;
#pragma unroll
        for (int p = 0; p < NP; p++) s[p] += sp[p];
    }
    float invd = g_invd[(b * NC + c) * HW + hw];
    float nv = EPSF;
#pragma unroll
    for (int p = 0; p < NP; p++) { s[p] *= invd; nv += s[p] * s[p]; }
    nv = sqrtf(nv);
    float f = 1.0f / (1.0f + nv);

    if (!LAST) {
        float fs = f * invd;                         // fold invd into stored v_s
        HPack pk;
#pragma unroll
        for (int j = 0; j < 8; j++)
            pk.h2[j] = __floats2half2_rn(s[2 * j] * fs, s[2 * j + 1] * fs);
        uint4* dst = reinterpret_cast<uint4*>(g_vs + ((size_t)((b * NC + c) * HW + hw)) * NP);
        dst[0] = pk.u4[0];
        dst[1] = pk.u4[1];
    } else {
        float an = EPSF;
#pragma unroll
        for (int p = 0; p < NP; p++) {
            float v = s[p] * f;
            vout[((b * NC + c) * NP + p) * HW + hw] = v;
            an += v * v;
        }
        aout[(b * NC + c) * HW + hw] = sqrtf(an);
    }
}

// ---------------- launch ------------------------------------------------------
extern "C" void kernel_launch(void* const* d_in, const int* in_sizes, int n_in,
                              void* d_out, int out_size) {
    const float* u = (const float*)d_in[0];
    float* out = (float*)d_out;
    float* out_v = out;                       // 4*32*16*196 = 401408
    float* out_a = out + BD * NC * NP * HW;   // 4*32*196    = 25088

    const int FGRID = BD * (HW / TH) * NCH2;  // 280

    kA1<<<392, 256>>>(u);                     // norms + Sum_B u + u16 transpose
    kA2<<<98, 256>>>();                       // inv_d, v0s
    kF<1><<<FGRID, FTHREADS>>>();             // r1 = dot(u,v0s); w1; S1 partials
    kC<0><<<98, 256>>>(nullptr, nullptr);     // v1s = invd*squash(invd*S1)
    kF<2><<<FGRID, FTHREADS>>>();             // r2 = r1+dot(u,v1s); w2; S2 partials
    kC<1><<<98, 256>>>(out_v, out_a);         // v2, a_out
}